// round 3
// baseline (speedup 1.0000x reference)
#include <cuda_runtime.h>

#define B 32
#define L 512
#define T 4096
#define D 384
#define D4 (D / 4)   // 96 float4 per row

// Scratch (no allocations allowed in kernel_launch)
__device__ int g_idx[B * T];
__device__ int g_total[B];

// Kernel 1: per-batch inclusive scan of durations + scatter token index into
// the output-slot map. Padding mask is folded in here: masked tokens scatter -1.
// NOTE: harness delivers int64 duration and bool mask both as int32.
__global__ void scan_scatter_kernel(const int* __restrict__ dur,
                                    const int* __restrict__ mask,
                                    float* __restrict__ out_tail,
                                    int write_tail) {
    __shared__ int s[L];
    const int b = blockIdx.x;
    const int t = threadIdx.x;

    const int d = dur[b * L + t];   // EXPAND_SCALE=1.0 -> round(d)=d
    s[t] = d;

    // Hillis-Steele inclusive scan over L=512
    #pragma unroll
    for (int off = 1; off < L; off <<= 1) {
        __syncthreads();
        int v = (t >= off) ? s[t - off] : 0;
        __syncthreads();
        s[t] += v;
    }
    __syncthreads();

    const int end   = s[t];
    const int start = end - d;
    const int val   = mask[b * L + t] ? -1 : t;
    for (int j = start; j < end; ++j)
        g_idx[b * T + j] = val;

    if (t == L - 1)
        g_total[b] = end;

    if (write_tail)
        out_tail[b * L + t] = (float)d;   // exp_dur as second output
}

// Kernel 2: gather-expand. One (96,4) block covers 4 output rows; each thread
// moves one float4. Coalesced writes; seq reads reuse L2 heavily (25 MB total).
__global__ void expand_kernel(const float4* __restrict__ seq,
                              float4* __restrict__ out) {
    const int row = blockIdx.x * 4 + threadIdx.y;   // 0 .. B*T-1
    const int c   = threadIdx.x;                    // 0 .. 95
    const int b   = row >> 12;                      // row / T
    const int j   = row & (T - 1);                  // row % T

    const int idx = g_idx[row];
    float4 v = make_float4(0.f, 0.f, 0.f, 0.f);
    if (j < g_total[b] && idx >= 0)
        v = seq[(b * L + idx) * D4 + c];
    out[row * D4 + c] = v;
}

extern "C" void kernel_launch(void* const* d_in, const int* in_sizes, int n_in,
                              void* d_out, int out_size) {
    const float* seq  = (const float*)d_in[0];
    const int*   dur  = (const int*)d_in[1];    // int64 in ref -> int32 here
    const int*   mask = (const int*)d_in[2];    // bool in ref -> int32 here
    float* out = (float*)d_out;

    const long long main_elems = (long long)B * T * D;
    const int write_tail = (out_size >= main_elems + (long long)B * L) ? 1 : 0;

    scan_scatter_kernel<<<B, L>>>(dur, mask, out + main_elems, write_tail);

    dim3 bd(D4, 4);                    // 96 x 4 = 384 threads
    expand_kernel<<<(B * T) / 4, bd>>>((const float4*)seq, (float4*)out);
}

// round 6
// speedup vs baseline: 1.3031x; 1.3031x over previous
#include <cuda_runtime.h>

#define B 32
#define L 512
#define T 4096
#define D 384
#define D4 (D / 4)          // 96 float4 per row
#define RPB 16              // rows per block in expand kernel
#define RPT 4               // rows per thread

// Scratch (no allocations allowed in kernel_launch)
__device__ int g_idx[B * T];
__device__ int g_total[B];

// Kernel 1: per-batch inclusive scan of durations + scatter token index into
// the output-slot map. Padding mask folded in: masked tokens scatter -1.
// NOTE: harness delivers int64 duration and bool mask both as int32.
__global__ void scan_scatter_kernel(const int* __restrict__ dur,
                                    const int* __restrict__ mask,
                                    float* __restrict__ out_tail,
                                    int write_tail) {
    __shared__ int s[L];
    const int b = blockIdx.x;
    const int t = threadIdx.x;

    const int d = dur[b * L + t];   // EXPAND_SCALE=1.0 -> round(d)=d
    s[t] = d;

    #pragma unroll
    for (int off = 1; off < L; off <<= 1) {
        __syncthreads();
        int v = (t >= off) ? s[t - off] : 0;
        __syncthreads();
        s[t] += v;
    }
    __syncthreads();

    const int end   = s[t];
    const int start = end - d;
    const int val   = mask[b * L + t] ? -1 : t;
    for (int j = start; j < end; ++j)
        g_idx[b * T + j] = val;

    if (t == L - 1)
        g_total[b] = end;

    if (write_tail)
        out_tail[b * L + t] = (float)d;   // exp_dur as second output
}

// Kernel 2: gather-expand with 4 rows per thread for MLP.
// Block (96,4) covers 16 consecutive output rows (all in one batch since
// T % 16 == 0). Thread (c,y) handles column c of rows base + y + {0,4,8,12}.
// Independent idx loads -> independent seq loads -> independent stores.
__global__ __launch_bounds__(D4 * 4)
void expand_kernel(const float4* __restrict__ seq,
                   float4* __restrict__ out) {
    const int base = blockIdx.x * RPB;
    const int c    = threadIdx.x;           // 0..95
    const int y    = threadIdx.y;           // 0..3
    const int b    = base >> 12;            // batch for all 16 rows
    const int tot  = g_total[b];

    int   row[RPT];
    int   idx[RPT];
    float4 v[RPT];

    #pragma unroll
    for (int i = 0; i < RPT; ++i) {
        row[i] = base + i * 4 + y;
        idx[i] = g_idx[row[i]];
    }

    #pragma unroll
    for (int i = 0; i < RPT; ++i) {
        const int j = row[i] & (T - 1);
        v[i] = make_float4(0.f, 0.f, 0.f, 0.f);
        if (j < tot && idx[i] >= 0)
            v[i] = seq[(b * L + idx[i]) * D4 + c];
    }

    #pragma unroll
    for (int i = 0; i < RPT; ++i)
        out[row[i] * D4 + c] = v[i];
}

extern "C" void kernel_launch(void* const* d_in, const int* in_sizes, int n_in,
                              void* d_out, int out_size) {
    const float* seq  = (const float*)d_in[0];
    const int*   dur  = (const int*)d_in[1];    // int64 in ref -> int32 here
    const int*   mask = (const int*)d_in[2];    // bool in ref -> int32 here
    float* out = (float*)d_out;

    const long long main_elems = (long long)B * T * D;
    const int write_tail = (out_size >= main_elems + (long long)B * L) ? 1 : 0;

    scan_scatter_kernel<<<B, L>>>(dur, mask, out + main_elems, write_tail);

    dim3 bd(D4, 4);                             // 384 threads
    expand_kernel<<<(B * T) / RPB, bd>>>((const float4*)seq, (float4*)out);
}

// round 9
// speedup vs baseline: 1.3144x; 1.0087x over previous
#include <cuda_runtime.h>

#define B 32
#define L 512
#define T 4096
#define D 384
#define D4 (D / 4)          // 96 float4 per row
#define RPT 8               // rows per thread in expand kernel
#define RPB (RPT * 4)       // 32 rows per block (block y-dim = 4)

// Scratch (no allocations allowed in kernel_launch)
__device__ int g_idx[B * T];
__device__ int g_total[B];

// Kernel 1: per-batch inclusive scan of durations (warp-shuffle scan) +
// scatter token index into the output-slot map. Padding mask folded in:
// masked tokens scatter -1. Harness delivers int64 dur / bool mask as int32.
__global__ void scan_scatter_kernel(const int* __restrict__ dur,
                                    const int* __restrict__ mask,
                                    float* __restrict__ out_tail,
                                    int write_tail) {
    __shared__ int wsum[16];
    const int b    = blockIdx.x;
    const int t    = threadIdx.x;        // 0..511
    const int lane = t & 31;
    const int w    = t >> 5;             // 0..15

    const int d = dur[b * L + t];        // EXPAND_SCALE=1.0 -> round(d)=d
    int x = d;

    // inclusive warp scan
    #pragma unroll
    for (int off = 1; off < 32; off <<= 1) {
        int n = __shfl_up_sync(0xFFFFFFFFu, x, off);
        if (lane >= off) x += n;
    }
    if (lane == 31) wsum[w] = x;
    __syncthreads();

    if (w == 0 && lane < 16) {
        int y = wsum[lane];
        #pragma unroll
        for (int off = 1; off < 16; off <<= 1) {
            int n = __shfl_up_sync(0xFFFFu, y, off);
            if (lane >= off) y += n;
        }
        wsum[lane] = y;
    }
    __syncthreads();

    const int end   = x + (w > 0 ? wsum[w - 1] : 0);
    const int start = end - d;
    const int val   = mask[b * L + t] ? -1 : t;
    for (int j = start; j < end; ++j)
        g_idx[b * T + j] = val;

    if (t == L - 1)
        g_total[b] = end;

    if (write_tail)
        out_tail[b * L + t] = (float)d;   // exp_dur as second output

    // PDL: signal the dependent expand_kernel as soon as our stores are done
    cudaTriggerProgrammaticLaunchCompletion();
}

// Kernel 2: gather-expand, 8 rows per thread for deep MLP.
// Block (96,4) covers 32 consecutive output rows (one batch: T % 32 == 0).
// Thread (c,y) handles column c of rows base + y + {0,4,...,28}.
__global__ __launch_bounds__(D4 * 4)
void expand_kernel(const float4* __restrict__ seq,
                   float4* __restrict__ out) {
    const int base = blockIdx.x * RPB;
    const int c    = threadIdx.x;           // 0..95
    const int y    = threadIdx.y;           // 0..3
    const int b    = base >> 12;            // batch for all 32 rows

    int row[RPT];
    #pragma unroll
    for (int i = 0; i < RPT; ++i)
        row[i] = base + i * 4 + y;

    // Wait for scan_scatter results (PDL overlap hides launch latency)
    cudaGridDependencySynchronize();

    const int tot = g_total[b];

    int idx[RPT];
    #pragma unroll
    for (int i = 0; i < RPT; ++i)
        idx[i] = g_idx[row[i]];

    float4 v[RPT];
    #pragma unroll
    for (int i = 0; i < RPT; ++i) {
        const int j = row[i] & (T - 1);
        v[i] = make_float4(0.f, 0.f, 0.f, 0.f);
        if (j < tot && idx[i] >= 0)
            v[i] = seq[(b * L + idx[i]) * D4 + c];
    }

    #pragma unroll
    for (int i = 0; i < RPT; ++i)
        out[row[i] * D4 + c] = v[i];
}

extern "C" void kernel_launch(void* const* d_in, const int* in_sizes, int n_in,
                              void* d_out, int out_size) {
    const float* seq  = (const float*)d_in[0];
    const int*   dur  = (const int*)d_in[1];    // int64 in ref -> int32 here
    const int*   mask = (const int*)d_in[2];    // bool in ref -> int32 here
    float* out = (float*)d_out;

    const long long main_elems = (long long)B * T * D;
    const int write_tail = (out_size >= main_elems + (long long)B * L) ? 1 : 0;

    scan_scatter_kernel<<<B, L>>>(dur, mask, out + main_elems, write_tail);

    // Programmatic dependent launch: expand starts early, syncs in-kernel.
    cudaLaunchConfig_t cfg = {};
    cfg.gridDim  = dim3((B * T) / RPB, 1, 1);
    cfg.blockDim = dim3(D4, 4, 1);
    cfg.dynamicSmemBytes = 0;
    cfg.stream = 0;
    cudaLaunchAttribute attr;
    attr.id = cudaLaunchAttributeProgrammaticStreamSerialization;
    attr.val.programmaticStreamSerializationAllowed = 1;
    cfg.attrs = &attr;
    cfg.numAttrs = 1;
    cudaLaunchKernelEx(&cfg, expand_kernel, (const float4*)seq, (float4*)out);
}